// round 2
// baseline (speedup 1.0000x reference)
#include <cuda_runtime.h>

#define NB 16384      // B
#define NK 50         // K
#define NH 64         // H
#define REG 0.01f

// Per-block partials: [0..NB) = mse, [NB..2NB) = sum||ie||, [2NB..3NB) = ||ue||
__device__ float g_part[3 * NB];
__device__ unsigned int g_count;   // zero-initialized; self-resets each run

__global__ __launch_bounds__(128, 8) void mf_main(
    const float* __restrict__ user_weight,   // [100000, 64]
    const float* __restrict__ item_weight,   // [1000000, 64]
    const float* __restrict__ user_bias,     // [100000, 1]
    const float* __restrict__ item_bias,     // [1000000, 1]
    const float* __restrict__ bias,          // [1]
    const float* __restrict__ target,        // [B, K]
    const int*   __restrict__ user,          // [B]
    const int*   __restrict__ item,          // [B, K]
    float* __restrict__ out)                 // [B*K + 1]
{
    const int b    = blockIdx.x;
    const int tid  = threadIdx.x;
    const int warp = tid >> 5;
    const int lane = tid & 31;

    __shared__ int   s_items[64];
    __shared__ float s_mse[4], s_ie[4];
    __shared__ bool  s_last;

    // Stage all item indices for this user once.
    if (tid < NK) s_items[tid] = item[b * NK + tid];

    // --- user embedding: ue = user_weight[u] + user_bias[u] ---
    const int u = user[b];
    const float ub = __ldg(user_bias + u);
    const float2 uw = __ldg((const float2*)(user_weight + (size_t)u * NH) + lane);
    const float uex = uw.x + ub;
    const float uey = uw.y + ub;
    const float bias0 = __ldg(bias);

    __syncthreads();

    // Warp k-ranges: 13,13,13,11
    const int kstart = warp * 13;
    const int kend   = min(NK, kstart + 13);

    float mse_acc = 0.0f;   // lane 0 only
    float ie_acc  = 0.0f;

    for (int k0 = kstart; k0 < kend; k0 += 4) {
        int    idx[4];
        float  ib[4];
        float2 v[4];

        // Issue ALL loads for the batch (MLP = 4 rows + 4 biases)
        #pragma unroll
        for (int j = 0; j < 4; j++) {
            const int kk = k0 + j;
            idx[j] = s_items[(kk < kend) ? kk : kstart];
        }
        #pragma unroll
        for (int j = 0; j < 4; j++)
            ib[j] = __ldg(item_bias + idx[j]);
        #pragma unroll
        for (int j = 0; j < 4; j++)
            v[j] = __ldg((const float2*)(item_weight + (size_t)idx[j] * NH) + lane);

        // Reduce each item
        #pragma unroll
        for (int j = 0; j < 4; j++) {
            const int kk = k0 + j;
            const float vx = v[j].x + ib[j];
            const float vy = v[j].y + ib[j];
            float d = fmaf(uex, vx, uey * vy);
            float s = fmaf(vx, vx, vy * vy);
            #pragma unroll
            for (int o = 16; o > 0; o >>= 1) {
                d += __shfl_xor_sync(0xffffffffu, d, o);
                s += __shfl_xor_sync(0xffffffffu, s, o);
            }
            if (lane == 0 && kk < kend) {
                const float pred = d + bias0;
                out[b * NK + kk] = pred;
                const float diff = pred - target[b * NK + kk];
                mse_acc = fmaf(diff, diff, mse_acc);
                ie_acc += sqrtf(s);
            }
        }
    }

    // --- ||ue|| on warp 0 (result lands on tid 0) ---
    float ue_norm = 0.0f;
    if (warp == 0) {
        float q = fmaf(uex, uex, uey * uey);
        #pragma unroll
        for (int o = 16; o > 0; o >>= 1)
            q += __shfl_xor_sync(0xffffffffu, q, o);
        ue_norm = sqrtf(q);
    }

    if (lane == 0) { s_mse[warp] = mse_acc; s_ie[warp] = ie_acc; }
    __syncthreads();

    if (tid == 0) {
        g_part[b]          = s_mse[0] + s_mse[1] + s_mse[2] + s_mse[3];
        g_part[NB + b]     = s_ie[0]  + s_ie[1]  + s_ie[2]  + s_ie[3];
        g_part[2 * NB + b] = ue_norm;
        __threadfence();
        const unsigned old = atomicAdd(&g_count, 1u);
        s_last = (old == (unsigned)(gridDim.x - 1));
    }
    __syncthreads();

    // --- last block: reduce all partials, write loss, reset counter ---
    if (s_last) {
        const float4* pm = (const float4*)(g_part);
        const float4* pe = (const float4*)(g_part + NB);
        const float4* pu = (const float4*)(g_part + 2 * NB);
        float4 am = make_float4(0, 0, 0, 0);
        float4 ae = make_float4(0, 0, 0, 0);
        float4 au = make_float4(0, 0, 0, 0);
        for (int i = tid; i < NB / 4; i += 128) {
            const float4 m4 = pm[i], e4 = pe[i], u4 = pu[i];
            am.x += m4.x; am.y += m4.y; am.z += m4.z; am.w += m4.w;
            ae.x += e4.x; ae.y += e4.y; ae.z += e4.z; ae.w += e4.w;
            au.x += u4.x; au.y += u4.y; au.z += u4.z; au.w += u4.w;
        }
        float m = (am.x + am.y) + (am.z + am.w);
        float e = (ae.x + ae.y) + (ae.z + ae.w);
        float un = (au.x + au.y) + (au.z + au.w);
        #pragma unroll
        for (int o = 16; o > 0; o >>= 1) {
            m  += __shfl_xor_sync(0xffffffffu, m, o);
            e  += __shfl_xor_sync(0xffffffffu, e, o);
            un += __shfl_xor_sync(0xffffffffu, un, o);
        }
        __shared__ float r_m[4], r_e[4], r_u[4];
        if (lane == 0) { r_m[warp] = m; r_e[warp] = e; r_u[warp] = un; }
        __syncthreads();
        if (tid == 0) {
            const float tm = r_m[0] + r_m[1] + r_m[2] + r_m[3];
            const float te = r_e[0] + r_e[1] + r_e[2] + r_e[3];
            const float tu = r_u[0] + r_u[1] + r_u[2] + r_u[3];
            const float n_bk = (float)NB * (float)NK;
            out[NB * NK] = tm / n_bk + REG * (tu / (float)NB) + REG * (te / n_bk);
            g_count = 0u;   // self-reset for next graph replay
        }
    }
}

extern "C" void kernel_launch(void* const* d_in, const int* in_sizes, int n_in,
                              void* d_out, int out_size) {
    const float* user_weight = (const float*)d_in[0];
    const float* item_weight = (const float*)d_in[1];
    const float* user_bias   = (const float*)d_in[2];
    const float* item_bias   = (const float*)d_in[3];
    const float* bias        = (const float*)d_in[4];
    const float* target      = (const float*)d_in[5];
    const int*   user        = (const int*)d_in[6];
    const int*   item        = (const int*)d_in[7];

    mf_main<<<NB, 128>>>(user_weight, item_weight, user_bias, item_bias,
                         bias, target, user, item, (float*)d_out);
}

// round 3
// speedup vs baseline: 2.2225x; 2.2225x over previous
#include <cuda_runtime.h>

#define NB 16384      // B
#define NK 50         // K
#define NH 64         // H
#define REG 0.01

__device__ double g_mse, g_ue, g_ie;        // zero-init; self-reset each run
__device__ unsigned int g_count;

__global__ __launch_bounds__(256, 4) void mf_main(
    const float* __restrict__ user_weight,   // [100000, 64]
    const float* __restrict__ item_weight,   // [1000000, 64]
    const float* __restrict__ user_bias,     // [100000, 1]
    const float* __restrict__ item_bias,     // [1000000, 1]
    const float* __restrict__ bias,          // [1]
    const float* __restrict__ target,        // [B, K]
    const int*   __restrict__ user,          // [B]
    const int*   __restrict__ item,          // [B, K]
    float* __restrict__ out)                 // [B*K + 1]
{
    const int tid  = threadIdx.x;
    const int warp = tid >> 5;               // 8 warps, one user each
    const int lane = tid & 31;
    const int g    = lane >> 3;              // group 0..3 (one item at a time)
    const int s    = lane & 7;               // sub-lane: H-slice owner
    const int b    = blockIdx.x * 8 + warp;

    __shared__ int s_items[8 * NK];

    // One coalesced read of all 8 users' item indices (400 ints).
    const int base = blockIdx.x * 8 * NK;
    for (int i = tid; i < 8 * NK; i += 256) s_items[i] = item[base + i];

    // --- user embedding slice: 8 floats per lane (same across groups) ---
    const int u = user[b];
    const float ubv = __ldg(user_bias + u);
    const float4* urow = (const float4*)(user_weight + (size_t)u * NH);
    float4 ua = __ldg(urow + s);
    float4 uc = __ldg(urow + 8 + s);
    ua.x += ubv; ua.y += ubv; ua.z += ubv; ua.w += ubv;
    uc.x += ubv; uc.y += ubv; uc.z += ubv; uc.w += ubv;
    const float bias0 = __ldg(bias);

    __syncthreads();
    const int* myitems = s_items + warp * NK;

    float mse_acc = 0.0f;   // valid on s==0 lanes
    float ie_acc  = 0.0f;

    // 12 full strided passes per group (k = g + 4*j), batch 2, fully unrolled.
    #pragma unroll
    for (int j0 = 0; j0 < 12; j0 += 2) {
        int   idx[2]; float ib[2]; float4 va[2], vc[2];
        #pragma unroll
        for (int j = 0; j < 2; j++) idx[j] = myitems[g + 4 * (j0 + j)];
        #pragma unroll
        for (int j = 0; j < 2; j++) ib[j] = __ldg(item_bias + idx[j]);
        #pragma unroll
        for (int j = 0; j < 2; j++) {
            const float4* r = (const float4*)(item_weight + (size_t)idx[j] * NH);
            va[j] = __ldg(r + s);
            vc[j] = __ldg(r + 8 + s);
        }
        #pragma unroll
        for (int j = 0; j < 2; j++) {
            const int k = g + 4 * (j0 + j);
            const float t = ib[j];
            float4 x = va[j], y = vc[j];
            x.x += t; x.y += t; x.z += t; x.w += t;
            y.x += t; y.y += t; y.z += t; y.w += t;
            float d = ua.x*x.x + ua.y*x.y + ua.z*x.z + ua.w*x.w
                    + uc.x*y.x + uc.y*y.y + uc.z*y.z + uc.w*y.w;
            float q = x.x*x.x + x.y*x.y + x.z*x.z + x.w*x.w
                    + y.x*y.x + y.y*y.y + y.z*y.z + y.w*y.w;
            #pragma unroll
            for (int o = 1; o < 8; o <<= 1) {
                d += __shfl_xor_sync(0xffffffffu, d, o);
                q += __shfl_xor_sync(0xffffffffu, q, o);
            }
            if (s == 0) {
                const float pred = d + bias0;
                out[b * NK + k] = pred;
                const float diff = pred - target[b * NK + k];
                mse_acc = fmaf(diff, diff, mse_acc);
                ie_acc += sqrtf(q);
            }
        }
    }

    // Tail: items 48, 49 handled by groups 0, 1.
    if (g < 2) {
        const int k = 48 + g;
        const int it = myitems[k];
        const float t = __ldg(item_bias + it);
        const float4* r = (const float4*)(item_weight + (size_t)it * NH);
        float4 x = __ldg(r + s), y = __ldg(r + 8 + s);
        x.x += t; x.y += t; x.z += t; x.w += t;
        y.x += t; y.y += t; y.z += t; y.w += t;
        float d = ua.x*x.x + ua.y*x.y + ua.z*x.z + ua.w*x.w
                + uc.x*y.x + uc.y*y.y + uc.z*y.z + uc.w*y.w;
        float q = x.x*x.x + x.y*x.y + x.z*x.z + x.w*x.w
                + y.x*y.x + y.y*y.y + y.z*y.z + y.w*y.w;
        #pragma unroll
        for (int o = 1; o < 8; o <<= 1) {
            d += __shfl_xor_sync(0x0000ffffu, d, o);
            q += __shfl_xor_sync(0x0000ffffu, q, o);
        }
        if (s == 0) {
            const float pred = d + bias0;
            out[b * NK + k] = pred;
            const float diff = pred - target[b * NK + k];
            mse_acc = fmaf(diff, diff, mse_acc);
            ie_acc += sqrtf(q);
        }
    }

    // --- ||ue||: per-lane q covers its 8 elems; group-0 reduce → lane 0 ---
    float uq = ua.x*ua.x + ua.y*ua.y + ua.z*ua.z + ua.w*ua.w
             + uc.x*uc.x + uc.y*uc.y + uc.z*uc.z + uc.w*uc.w;
    #pragma unroll
    for (int o = 1; o < 8; o <<= 1)
        uq += __shfl_xor_sync(0xffffffffu, uq, o);
    const float ue_n = sqrtf(uq);            // valid on every s==0 lane

    // Warp-reduce mse/ie across the four s==0 lanes (0,8,16,24).
    float m = (s == 0) ? mse_acc : 0.0f;
    float e = (s == 0) ? ie_acc  : 0.0f;
    m += __shfl_xor_sync(0xffffffffu, m, 8);
    m += __shfl_xor_sync(0xffffffffu, m, 16);
    e += __shfl_xor_sync(0xffffffffu, e, 8);
    e += __shfl_xor_sync(0xffffffffu, e, 16);

    __shared__ float sm[8], se[8], su[8];
    if (lane == 0) { sm[warp] = m; se[warp] = e; su[warp] = ue_n; }
    __syncthreads();

    if (tid == 0) {
        float tm = 0.f, te = 0.f, tu = 0.f;
        #pragma unroll
        for (int i = 0; i < 8; i++) { tm += sm[i]; te += se[i]; tu += su[i]; }
        atomicAdd(&g_mse, (double)tm);
        atomicAdd(&g_ie,  (double)te);
        atomicAdd(&g_ue,  (double)tu);
        __threadfence();
        const unsigned old = atomicAdd(&g_count, 1u);
        if (old == gridDim.x - 1) {
            // Atomically read-and-reset accumulators (safe for graph replay).
            unsigned long long mb = atomicExch((unsigned long long*)&g_mse, 0ull);
            unsigned long long eb = atomicExch((unsigned long long*)&g_ie,  0ull);
            unsigned long long ub2 = atomicExch((unsigned long long*)&g_ue, 0ull);
            const double mse = __longlong_as_double((long long)mb);
            const double ie  = __longlong_as_double((long long)eb);
            const double ue  = __longlong_as_double((long long)ub2);
            const double n_bk = (double)NB * (double)NK;
            out[NB * NK] = (float)(mse / n_bk + REG * (ue / (double)NB)
                                              + REG * (ie / n_bk));
            atomicExch(&g_count, 0u);
        }
    }
}

extern "C" void kernel_launch(void* const* d_in, const int* in_sizes, int n_in,
                              void* d_out, int out_size) {
    const float* user_weight = (const float*)d_in[0];
    const float* item_weight = (const float*)d_in[1];
    const float* user_bias   = (const float*)d_in[2];
    const float* item_bias   = (const float*)d_in[3];
    const float* bias        = (const float*)d_in[4];
    const float* target      = (const float*)d_in[5];
    const int*   user        = (const int*)d_in[6];
    const int*   item        = (const int*)d_in[7];

    mf_main<<<NB / 8, 256>>>(user_weight, item_weight, user_bias, item_bias,
                             bias, target, user, item, (float*)d_out);
}

// round 4
// speedup vs baseline: 2.3133x; 1.0409x over previous
#include <cuda_runtime.h>

#define NB 16384      // B
#define NK 50         // K
#define NH 64         // H
#define REG 0.01

typedef unsigned long long u64;

static __device__ __forceinline__ u64 pack2(float lo, float hi) {
    u64 r; asm("mov.b64 %0, {%1,%2};" : "=l"(r) : "f"(lo), "f"(hi)); return r;
}
static __device__ __forceinline__ void unpack2(u64 v, float& lo, float& hi) {
    asm("mov.b64 {%0,%1}, %2;" : "=f"(lo), "=f"(hi) : "l"(v));
}
static __device__ __forceinline__ u64 add2(u64 a, u64 b) {
    u64 r; asm("add.rn.f32x2 %0, %1, %2;" : "=l"(r) : "l"(a), "l"(b)); return r;
}
static __device__ __forceinline__ u64 mul2(u64 a, u64 b) {
    u64 r; asm("mul.rn.f32x2 %0, %1, %2;" : "=l"(r) : "l"(a), "l"(b)); return r;
}
static __device__ __forceinline__ u64 fma2(u64 a, u64 b, u64 c) {
    u64 r; asm("fma.rn.f32x2 %0, %1, %2, %3;" : "=l"(r) : "l"(a), "l"(b), "l"(c)); return r;
}

__device__ double g_mse, g_ue, g_ie;        // zero-init; self-reset each run
__device__ unsigned int g_count;

__global__ __launch_bounds__(256, 6) void mf_main(
    const float* __restrict__ user_weight,   // [100000, 64]
    const float* __restrict__ item_weight,   // [1000000, 64]
    const float* __restrict__ user_bias,     // [100000, 1]
    const float* __restrict__ item_bias,     // [1000000, 1]
    const float* __restrict__ bias,          // [1]
    const float* __restrict__ target,        // [B, K]
    const int*   __restrict__ user,          // [B]
    const int*   __restrict__ item,          // [B, K]
    float* __restrict__ out)                 // [B*K + 1]
{
    const int tid  = threadIdx.x;
    const int warp = tid >> 5;               // 8 warps, one user each
    const int lane = tid & 31;
    const int g    = lane >> 3;              // group 0..3 within warp
    const int s    = lane & 7;               // H-slice owner (16B each)
    const int b    = blockIdx.x * 8 + warp;

    __shared__ int s_items[8 * NK];

    const int base = blockIdx.x * 8 * NK;
    for (int i = tid; i < 8 * NK; i += 256) s_items[i] = item[base + i];

    // --- user embedding slice, packed as 4 f32x2 pairs ---
    const int u = user[b];
    const float ubv = __ldg(user_bias + u);
    const u64 ubp = pack2(ubv, ubv);
    const ulonglong2* urow = (const ulonglong2*)(user_weight + (size_t)u * NH);
    ulonglong2 ur0 = __ldg(urow + s);
    ulonglong2 ur1 = __ldg(urow + 8 + s);
    const u64 u0 = add2(ur0.x, ubp);
    const u64 u1 = add2(ur0.y, ubp);
    const u64 u2 = add2(ur1.x, ubp);
    const u64 u3 = add2(ur1.y, ubp);
    const float bias0 = __ldg(bias);

    __syncthreads();
    const int* myitems = s_items + warp * NK;

    float mse_acc = 0.0f;   // valid on s==0 lanes
    float ie_acc  = 0.0f;

    // 12 strided passes per group (k = g + 4*j), batch 2.
    #pragma unroll
    for (int j0 = 0; j0 < 12; j0 += 2) {
        int idx0 = myitems[g + 4 * j0];
        int idx1 = myitems[g + 4 * (j0 + 1)];
        float ib0 = __ldg(item_bias + idx0);
        float ib1 = __ldg(item_bias + idx1);
        const ulonglong2* r0 = (const ulonglong2*)(item_weight + (size_t)idx0 * NH);
        const ulonglong2* r1 = (const ulonglong2*)(item_weight + (size_t)idx1 * NH);
        ulonglong2 a0 = __ldg(r0 + s), c0 = __ldg(r0 + 8 + s);
        ulonglong2 a1 = __ldg(r1 + s), c1 = __ldg(r1 + 8 + s);

        #pragma unroll
        for (int j = 0; j < 2; j++) {
            const int k = g + 4 * (j0 + j);
            const ulonglong2 a = j ? a1 : a0;
            const ulonglong2 c = j ? c1 : c0;
            const u64 ibp = pack2(j ? ib1 : ib0, j ? ib1 : ib0);
            const u64 x0 = add2(a.x, ibp), x1 = add2(a.y, ibp);
            const u64 x2 = add2(c.x, ibp), x3 = add2(c.y, ibp);
            u64 d2 = mul2(u0, x0); d2 = fma2(u1, x1, d2);
            d2 = fma2(u2, x2, d2); d2 = fma2(u3, x3, d2);
            u64 q2 = mul2(x0, x0); q2 = fma2(x1, x1, q2);
            q2 = fma2(x2, x2, q2); q2 = fma2(x3, x3, q2);
            float dl, dh, ql, qh;
            unpack2(d2, dl, dh); unpack2(q2, ql, qh);
            float d = dl + dh, q = ql + qh;
            #pragma unroll
            for (int o = 1; o < 8; o <<= 1) {
                d += __shfl_xor_sync(0xffffffffu, d, o);
                q += __shfl_xor_sync(0xffffffffu, q, o);
            }
            if (s == 0) {
                const float pred = d + bias0;
                __stcs(out + b * NK + k, pred);
                const float diff = pred - __ldcs(target + b * NK + k);
                mse_acc = fmaf(diff, diff, mse_acc);
                ie_acc += sqrtf(q);
            }
        }
    }

    // Tail: items 48, 49 handled by groups 0, 1.
    if (g < 2) {
        const int k = 48 + g;
        const int it = myitems[k];
        const float ib = __ldg(item_bias + it);
        const ulonglong2* r = (const ulonglong2*)(item_weight + (size_t)it * NH);
        ulonglong2 a = __ldg(r + s), c = __ldg(r + 8 + s);
        const u64 ibp = pack2(ib, ib);
        const u64 x0 = add2(a.x, ibp), x1 = add2(a.y, ibp);
        const u64 x2 = add2(c.x, ibp), x3 = add2(c.y, ibp);
        u64 d2 = mul2(u0, x0); d2 = fma2(u1, x1, d2);
        d2 = fma2(u2, x2, d2); d2 = fma2(u3, x3, d2);
        u64 q2 = mul2(x0, x0); q2 = fma2(x1, x1, q2);
        q2 = fma2(x2, x2, q2); q2 = fma2(x3, x3, q2);
        float dl, dh, ql, qh;
        unpack2(d2, dl, dh); unpack2(q2, ql, qh);
        float d = dl + dh, q = ql + qh;
        #pragma unroll
        for (int o = 1; o < 8; o <<= 1) {
            d += __shfl_xor_sync(0x0000ffffu, d, o);
            q += __shfl_xor_sync(0x0000ffffu, q, o);
        }
        if (s == 0) {
            const float pred = d + bias0;
            __stcs(out + b * NK + k, pred);
            const float diff = pred - __ldcs(target + b * NK + k);
            mse_acc = fmaf(diff, diff, mse_acc);
            ie_acc += sqrtf(q);
        }
    }

    // --- ||ue|| ---
    u64 uq2 = mul2(u0, u0); uq2 = fma2(u1, u1, uq2);
    uq2 = fma2(u2, u2, uq2); uq2 = fma2(u3, u3, uq2);
    float ul, uh; unpack2(uq2, ul, uh);
    float uq = ul + uh;
    #pragma unroll
    for (int o = 1; o < 8; o <<= 1)
        uq += __shfl_xor_sync(0xffffffffu, uq, o);
    const float ue_n = sqrtf(uq);             // valid on every s==0 lane

    // Warp-reduce mse/ie across s==0 lanes (0,8,16,24).
    float m = (s == 0) ? mse_acc : 0.0f;
    float e = (s == 0) ? ie_acc  : 0.0f;
    m += __shfl_xor_sync(0xffffffffu, m, 8);
    m += __shfl_xor_sync(0xffffffffu, m, 16);
    e += __shfl_xor_sync(0xffffffffu, e, 8);
    e += __shfl_xor_sync(0xffffffffu, e, 16);

    __shared__ float sm[8], se[8], su[8];
    if (lane == 0) { sm[warp] = m; se[warp] = e; su[warp] = ue_n; }
    __syncthreads();

    if (tid == 0) {
        float tm = 0.f, te = 0.f, tu = 0.f;
        #pragma unroll
        for (int i = 0; i < 8; i++) { tm += sm[i]; te += se[i]; tu += su[i]; }
        atomicAdd(&g_mse, (double)tm);
        atomicAdd(&g_ie,  (double)te);
        atomicAdd(&g_ue,  (double)tu);
        __threadfence();
        const unsigned old = atomicAdd(&g_count, 1u);
        if (old == gridDim.x - 1) {
            u64 mb  = atomicExch((u64*)&g_mse, 0ull);
            u64 eb  = atomicExch((u64*)&g_ie,  0ull);
            u64 ub2 = atomicExch((u64*)&g_ue,  0ull);
            const double mse = __longlong_as_double((long long)mb);
            const double ie  = __longlong_as_double((long long)eb);
            const double ue  = __longlong_as_double((long long)ub2);
            const double n_bk = (double)NB * (double)NK;
            out[NB * NK] = (float)(mse / n_bk + REG * (ue / (double)NB)
                                              + REG * (ie / n_bk));
            atomicExch(&g_count, 0u);
        }
    }
}

extern "C" void kernel_launch(void* const* d_in, const int* in_sizes, int n_in,
                              void* d_out, int out_size) {
    const float* user_weight = (const float*)d_in[0];
    const float* item_weight = (const float*)d_in[1];
    const float* user_bias   = (const float*)d_in[2];
    const float* item_bias   = (const float*)d_in[3];
    const float* bias        = (const float*)d_in[4];
    const float* target      = (const float*)d_in[5];
    const int*   user        = (const int*)d_in[6];
    const int*   item        = (const int*)d_in[7];

    mf_main<<<NB / 8, 256>>>(user_weight, item_weight, user_bias, item_bias,
                             bias, target, user, item, (float*)d_out);
}

// round 5
// speedup vs baseline: 2.5801x; 1.1153x over previous
#include <cuda_runtime.h>

#define NB 16384      // B
#define NK 50         // K
#define NH 64         // H
#define REG 0.01

typedef unsigned long long u64;

static __device__ __forceinline__ u64 pack2(float lo, float hi) {
    u64 r; asm("mov.b64 %0, {%1,%2};" : "=l"(r) : "f"(lo), "f"(hi)); return r;
}
static __device__ __forceinline__ void unpack2(u64 v, float& lo, float& hi) {
    asm("mov.b64 {%0,%1}, %2;" : "=f"(lo), "=f"(hi) : "l"(v));
}
static __device__ __forceinline__ u64 add2(u64 a, u64 b) {
    u64 r; asm("add.rn.f32x2 %0, %1, %2;" : "=l"(r) : "l"(a), "l"(b)); return r;
}
static __device__ __forceinline__ u64 mul2(u64 a, u64 b) {
    u64 r; asm("mul.rn.f32x2 %0, %1, %2;" : "=l"(r) : "l"(a), "l"(b)); return r;
}
static __device__ __forceinline__ u64 fma2(u64 a, u64 b, u64 c) {
    u64 r; asm("fma.rn.f32x2 %0, %1, %2, %3;" : "=l"(r) : "l"(a), "l"(b), "l"(c)); return r;
}

__device__ double g_mse, g_ue, g_ie;        // zero-init; self-reset each run
__device__ unsigned int g_count;

__global__ __launch_bounds__(256, 5) void mf_main(
    const float* __restrict__ user_weight,   // [100000, 64]
    const float* __restrict__ item_weight,   // [1000000, 64]
    const float* __restrict__ user_bias,     // [100000, 1]
    const float* __restrict__ item_bias,     // [1000000, 1]
    const float* __restrict__ bias,          // [1]
    const float* __restrict__ target,        // [B, K]
    const int*   __restrict__ user,          // [B]
    const int*   __restrict__ item,          // [B, K]
    float* __restrict__ out)                 // [B*K + 1]
{
    const int tid  = threadIdx.x;
    const int warp = tid >> 5;               // 8 warps, one user each
    const int lane = tid & 31;
    const int g    = lane >> 3;              // group 0..3 within warp
    const int s    = lane & 7;               // H-slice owner (16B each)
    const int b    = blockIdx.x * 8 + warp;

    __shared__ int s_items[8 * NK];

    const int base = blockIdx.x * 8 * NK;
    for (int i = tid; i < 8 * NK; i += 256) s_items[i] = item[base + i];

    // --- user embedding slice, packed as 4 f32x2 pairs ---
    const int u = user[b];
    const float ubv = __ldg(user_bias + u);
    const u64 ubp = pack2(ubv, ubv);
    const ulonglong2* urow = (const ulonglong2*)(user_weight + (size_t)u * NH);
    ulonglong2 ur0 = __ldg(urow + s);
    ulonglong2 ur1 = __ldg(urow + 8 + s);
    const u64 u0 = add2(ur0.x, ubp);
    const u64 u1 = add2(ur0.y, ubp);
    const u64 u2 = add2(ur1.x, ubp);
    const u64 u3 = add2(ur1.y, ubp);
    const float bias0 = __ldg(bias);

    __syncthreads();
    const int* myitems = s_items + warp * NK;

    float mse_acc = 0.0f;   // valid on s==0 lanes
    float ie_acc  = 0.0f;

    // ---- software-pipelined mainloop: 6 batches of 2 items per group ----
    // Buffers (double-buffered; unroll promotes to registers).
    float      ib[2][2];
    ulonglong2 va[2][2], vc[2][2];

    // Prologue: load batch 0 into buffer 0.
    {
        const int i0 = myitems[g + 0];
        const int i1 = myitems[g + 4];
        ib[0][0] = __ldg(item_bias + i0);
        ib[0][1] = __ldg(item_bias + i1);
        const ulonglong2* r0 = (const ulonglong2*)(item_weight + (size_t)i0 * NH);
        const ulonglong2* r1 = (const ulonglong2*)(item_weight + (size_t)i1 * NH);
        va[0][0] = __ldg(r0 + s); vc[0][0] = __ldg(r0 + 8 + s);
        va[0][1] = __ldg(r1 + s); vc[0][1] = __ldg(r1 + 8 + s);
    }

    #pragma unroll
    for (int t = 0; t < 6; t++) {
        const int cur = t & 1, nxt = cur ^ 1;

        // Issue next batch's loads BEFORE consuming current batch.
        if (t < 5) {
            const int i0 = myitems[g + 4 * (2 * t + 2)];
            const int i1 = myitems[g + 4 * (2 * t + 3)];
            ib[nxt][0] = __ldg(item_bias + i0);
            ib[nxt][1] = __ldg(item_bias + i1);
            const ulonglong2* r0 = (const ulonglong2*)(item_weight + (size_t)i0 * NH);
            const ulonglong2* r1 = (const ulonglong2*)(item_weight + (size_t)i1 * NH);
            va[nxt][0] = __ldg(r0 + s); vc[nxt][0] = __ldg(r0 + 8 + s);
            va[nxt][1] = __ldg(r1 + s); vc[nxt][1] = __ldg(r1 + 8 + s);
        }

        // Consume current batch.
        #pragma unroll
        for (int j = 0; j < 2; j++) {
            const int k = g + 4 * (2 * t + j);
            const u64 ibp = pack2(ib[cur][j], ib[cur][j]);
            const u64 x0 = add2(va[cur][j].x, ibp), x1 = add2(va[cur][j].y, ibp);
            const u64 x2 = add2(vc[cur][j].x, ibp), x3 = add2(vc[cur][j].y, ibp);
            u64 d2 = mul2(u0, x0); d2 = fma2(u1, x1, d2);
            d2 = fma2(u2, x2, d2); d2 = fma2(u3, x3, d2);
            u64 q2 = mul2(x0, x0); q2 = fma2(x1, x1, q2);
            q2 = fma2(x2, x2, q2); q2 = fma2(x3, x3, q2);
            float dl, dh, ql, qh;
            unpack2(d2, dl, dh); unpack2(q2, ql, qh);
            float d = dl + dh, q = ql + qh;
            #pragma unroll
            for (int o = 1; o < 8; o <<= 1) {
                d += __shfl_xor_sync(0xffffffffu, d, o);
                q += __shfl_xor_sync(0xffffffffu, q, o);
            }
            if (s == 0) {
                const float pred = d + bias0;
                __stcs(out + b * NK + k, pred);
                const float diff = pred - __ldcs(target + b * NK + k);
                mse_acc = fmaf(diff, diff, mse_acc);
                ie_acc += sqrtf(q);
            }
        }
    }

    // Tail: items 48, 49 handled by groups 0, 1.
    if (g < 2) {
        const int k = 48 + g;
        const int it = myitems[k];
        const float ibt = __ldg(item_bias + it);
        const ulonglong2* r = (const ulonglong2*)(item_weight + (size_t)it * NH);
        ulonglong2 a = __ldg(r + s), c = __ldg(r + 8 + s);
        const u64 ibp = pack2(ibt, ibt);
        const u64 x0 = add2(a.x, ibp), x1 = add2(a.y, ibp);
        const u64 x2 = add2(c.x, ibp), x3 = add2(c.y, ibp);
        u64 d2 = mul2(u0, x0); d2 = fma2(u1, x1, d2);
        d2 = fma2(u2, x2, d2); d2 = fma2(u3, x3, d2);
        u64 q2 = mul2(x0, x0); q2 = fma2(x1, x1, q2);
        q2 = fma2(x2, x2, q2); q2 = fma2(x3, x3, q2);
        float dl, dh, ql, qh;
        unpack2(d2, dl, dh); unpack2(q2, ql, qh);
        float d = dl + dh, q = ql + qh;
        #pragma unroll
        for (int o = 1; o < 8; o <<= 1) {
            d += __shfl_xor_sync(0x0000ffffu, d, o);
            q += __shfl_xor_sync(0x0000ffffu, q, o);
        }
        if (s == 0) {
            const float pred = d + bias0;
            __stcs(out + b * NK + k, pred);
            const float diff = pred - __ldcs(target + b * NK + k);
            mse_acc = fmaf(diff, diff, mse_acc);
            ie_acc += sqrtf(q);
        }
    }

    // --- ||ue|| ---
    u64 uq2 = mul2(u0, u0); uq2 = fma2(u1, u1, uq2);
    uq2 = fma2(u2, u2, uq2); uq2 = fma2(u3, u3, uq2);
    float ul, uh; unpack2(uq2, ul, uh);
    float uq = ul + uh;
    #pragma unroll
    for (int o = 1; o < 8; o <<= 1)
        uq += __shfl_xor_sync(0xffffffffu, uq, o);
    const float ue_n = sqrtf(uq);             // valid on every s==0 lane

    // Warp-reduce mse/ie across s==0 lanes (0,8,16,24).
    float m = (s == 0) ? mse_acc : 0.0f;
    float e = (s == 0) ? ie_acc  : 0.0f;
    m += __shfl_xor_sync(0xffffffffu, m, 8);
    m += __shfl_xor_sync(0xffffffffu, m, 16);
    e += __shfl_xor_sync(0xffffffffu, e, 8);
    e += __shfl_xor_sync(0xffffffffu, e, 16);

    __shared__ float sm[8], se[8], su[8];
    if (lane == 0) { sm[warp] = m; se[warp] = e; su[warp] = ue_n; }
    __syncthreads();

    if (tid == 0) {
        float tm = 0.f, te = 0.f, tu = 0.f;
        #pragma unroll
        for (int i = 0; i < 8; i++) { tm += sm[i]; te += se[i]; tu += su[i]; }
        atomicAdd(&g_mse, (double)tm);
        atomicAdd(&g_ie,  (double)te);
        atomicAdd(&g_ue,  (double)tu);
        __threadfence();
        const unsigned old = atomicAdd(&g_count, 1u);
        if (old == gridDim.x - 1) {
            u64 mb  = atomicExch((u64*)&g_mse, 0ull);
            u64 eb  = atomicExch((u64*)&g_ie,  0ull);
            u64 ub2 = atomicExch((u64*)&g_ue,  0ull);
            const double mse = __longlong_as_double((long long)mb);
            const double ie  = __longlong_as_double((long long)eb);
            const double ue  = __longlong_as_double((long long)ub2);
            const double n_bk = (double)NB * (double)NK;
            out[NB * NK] = (float)(mse / n_bk + REG * (ue / (double)NB)
                                              + REG * (ie / n_bk));
            atomicExch(&g_count, 0u);
        }
    }
}

extern "C" void kernel_launch(void* const* d_in, const int* in_sizes, int n_in,
                              void* d_out, int out_size) {
    const float* user_weight = (const float*)d_in[0];
    const float* item_weight = (const float*)d_in[1];
    const float* user_bias   = (const float*)d_in[2];
    const float* item_bias   = (const float*)d_in[3];
    const float* bias        = (const float*)d_in[4];
    const float* target      = (const float*)d_in[5];
    const int*   user        = (const int*)d_in[6];
    const int*   item        = (const int*)d_in[7];

    mf_main<<<NB / 8, 256>>>(user_weight, item_weight, user_bias, item_bias,
                             bias, target, user, item, (float*)d_out);
}

// round 7
// speedup vs baseline: 2.6496x; 1.0270x over previous
#include <cuda_runtime.h>
#include <cstdint>

#define NB 16384      // B
#define NK 50         // K
#define NH 64         // H
#define REG 0.01
#define DEPTH 4       // cp.async ring depth (stages)
#define NSTAGE 13     // 12 full stages of 4 items + 1 tail stage of 2

typedef unsigned long long u64;

static __device__ __forceinline__ u64 pack2(float lo, float hi) {
    u64 r; asm("mov.b64 %0, {%1,%2};" : "=l"(r) : "f"(lo), "f"(hi)); return r;
}
static __device__ __forceinline__ void unpack2(u64 v, float& lo, float& hi) {
    asm("mov.b64 {%0,%1}, %2;" : "=f"(lo), "=f"(hi) : "l"(v));
}
static __device__ __forceinline__ u64 add2(u64 a, u64 b) {
    u64 r; asm("add.rn.f32x2 %0, %1, %2;" : "=l"(r) : "l"(a), "l"(b)); return r;
}
static __device__ __forceinline__ u64 mul2(u64 a, u64 b) {
    u64 r; asm("mul.rn.f32x2 %0, %1, %2;" : "=l"(r) : "l"(a), "l"(b)); return r;
}
static __device__ __forceinline__ u64 fma2(u64 a, u64 b, u64 c) {
    u64 r; asm("fma.rn.f32x2 %0, %1, %2, %3;" : "=l"(r) : "l"(a), "l"(b), "l"(c)); return r;
}
static __device__ __forceinline__ void cpa16(uint32_t dst, const void* src) {
    asm volatile("cp.async.cg.shared.global [%0], [%1], 16;\n" :: "r"(dst), "l"(src));
}

__device__ double g_mse, g_ue, g_ie;        // zero-init; self-reset each run
__device__ unsigned int g_count;

__global__ __launch_bounds__(256, 5) void mf_main(
    const float* __restrict__ user_weight,   // [100000, 64]
    const float* __restrict__ item_weight,   // [1000000, 64]
    const float* __restrict__ user_bias,     // [100000, 1]
    const float* __restrict__ item_bias,     // [1000000, 1]
    const float* __restrict__ bias,          // [1]
    const float* __restrict__ target,        // [B, K]
    const int*   __restrict__ user,          // [B]
    const int*   __restrict__ item,          // [B, K]
    float* __restrict__ out)                 // [B*K + 1]
{
    const int tid  = threadIdx.x;
    const int warp = tid >> 5;               // 8 warps, one user each
    const int lane = tid & 31;
    const int g    = lane >> 3;              // group 0..3 within warp
    const int s    = lane & 7;               // H-slice owner (32B each)
    const int b    = blockIdx.x * 8 + warp;

    __shared__ int   s_items[8 * NK];
    __shared__ float s_pred[8 * NK];
    __shared__ __align__(16) char s_ring[8 * DEPTH * 4 * 256];  // 32 KB

    const int base = blockIdx.x * 8 * NK;
    for (int i = tid; i < 8 * NK; i += 256) s_items[i] = item[base + i];

    // --- user embedding slice: CONTIGUOUS floats [8s .. 8s+7] (matches the
    //     item slice layout used by the cp.async ring) ---
    const int u = user[b];
    const float ubv = __ldg(user_bias + u);
    const u64 ubp = pack2(ubv, ubv);
    const float* uwr = user_weight + (size_t)u * NH + s * 8;
    ulonglong2 ur0 = __ldg((const ulonglong2*)uwr);
    ulonglong2 ur1 = __ldg((const ulonglong2*)(uwr + 4));
    const u64 u0 = add2(ur0.x, ubp);
    const u64 u1 = add2(ur0.y, ubp);
    const u64 u2 = add2(ur1.x, ubp);
    const u64 u3 = add2(ur1.y, ubp);
    const float bias0 = __ldg(bias);

    __syncthreads();
    const int* myitems = s_items + warp * NK;
    const uint32_t my_ring =
        (uint32_t)__cvta_generic_to_shared(s_ring) + warp * (DEPTH * 1024)
        + g * 256 + s * 32;

    // stage t item index for this group (tail stage: groups >=2 fetch a dummy
    // valid row, never consumed)
    #define STAGE_K(t) (((t) < 12) ? (4 * (t) + g) : ((g < 2) ? (48 + g) : g))

    // --- prologue: fill stages 0..DEPTH-2 ---
    #pragma unroll
    for (int t = 0; t < DEPTH - 1; t++) {
        const int idx = myitems[STAGE_K(t)];
        const float* row = item_weight + (size_t)idx * NH + s * 8;
        const uint32_t dst = my_ring + (t & (DEPTH - 1)) * 1024;
        cpa16(dst, row);
        cpa16(dst + 16, row + 4);
        asm volatile("cp.async.commit_group;\n");
    }
    // bias register pipeline (depth 2)
    float fb[2];
    fb[0] = __ldg(item_bias + myitems[STAGE_K(0)]);
    fb[1] = __ldg(item_bias + myitems[STAGE_K(1)]);

    float ie_acc = 0.0f;                     // valid on s==0 lanes

    #pragma unroll
    for (int t = 0; t < NSTAGE; t++) {
        // issue stage t+DEPTH-1 (commit empty groups near the end to keep
        // wait_group counting uniform)
        if (t + DEPTH - 1 < NSTAGE) {
            const int tt = t + DEPTH - 1;
            const int idx = myitems[STAGE_K(tt)];
            const float* row = item_weight + (size_t)idx * NH + s * 8;
            const uint32_t dst = my_ring + (tt & (DEPTH - 1)) * 1024;
            cpa16(dst, row);
            cpa16(dst + 16, row + 4);
        }
        asm volatile("cp.async.commit_group;\n");

        const float ib = fb[t & 1];
        if (t + 2 < NSTAGE)
            fb[t & 1] = __ldg(item_bias + myitems[STAGE_K(t + 2)]);

        // stage t guaranteed complete when <= DEPTH-1 newer groups pending
        asm volatile("cp.async.wait_group %0;\n" :: "n"(DEPTH - 1));

        // consume own 32B slice (written by this lane -> no sync needed)
        const uint32_t srcp = my_ring + (t & (DEPTH - 1)) * 1024;
        u64 x0, x1, x2, x3;
        asm volatile("ld.shared.v2.u64 {%0,%1}, [%2];"
                     : "=l"(x0), "=l"(x1) : "r"(srcp));
        asm volatile("ld.shared.v2.u64 {%0,%1}, [%2];"
                     : "=l"(x2), "=l"(x3) : "r"(srcp + 16));

        const u64 ibp = pack2(ib, ib);
        x0 = add2(x0, ibp); x1 = add2(x1, ibp);
        x2 = add2(x2, ibp); x3 = add2(x3, ibp);
        u64 d2 = mul2(u0, x0); d2 = fma2(u1, x1, d2);
        d2 = fma2(u2, x2, d2); d2 = fma2(u3, x3, d2);
        u64 q2 = mul2(x0, x0); q2 = fma2(x1, x1, q2);
        q2 = fma2(x2, x2, q2); q2 = fma2(x3, x3, q2);
        float dl, dh, ql, qh;
        unpack2(d2, dl, dh); unpack2(q2, ql, qh);
        float d = dl + dh, q = ql + qh;
        #pragma unroll
        for (int o = 1; o < 8; o <<= 1) {
            d += __shfl_xor_sync(0xffffffffu, d, o);
            q += __shfl_xor_sync(0xffffffffu, q, o);
        }
        const bool active = (t < 12) || (g < 2);
        if (s == 0 && active) {
            s_pred[warp * NK + STAGE_K(t)] = d + bias0;
            ie_acc += sqrtf(q);
        }
    }
    #undef STAGE_K

    __syncwarp();

    // --- coalesced epilogue: preds out, targets in, mse per lane ---
    float mse_acc = 0.0f;
    #pragma unroll
    for (int i = lane; i < NK; i += 32) {
        const float pred = s_pred[warp * NK + i];
        const float diff = pred - __ldcs(target + b * NK + i);
        mse_acc = fmaf(diff, diff, mse_acc);
        __stcs(out + b * NK + i, pred);
    }
    #pragma unroll
    for (int o = 1; o < 32; o <<= 1)
        mse_acc += __shfl_xor_sync(0xffffffffu, mse_acc, o);

    // --- ||ue|| ---
    u64 uq2 = mul2(u0, u0); uq2 = fma2(u1, u1, uq2);
    uq2 = fma2(u2, u2, uq2); uq2 = fma2(u3, u3, uq2);
    float ul, uh; unpack2(uq2, ul, uh);
    float uq = ul + uh;
    #pragma unroll
    for (int o = 1; o < 8; o <<= 1)
        uq += __shfl_xor_sync(0xffffffffu, uq, o);
    const float ue_n = sqrtf(uq);             // valid on every s==0 lane

    // reduce ie across the four s==0 lanes (0,8,16,24)
    float e = (s == 0) ? ie_acc : 0.0f;
    e += __shfl_xor_sync(0xffffffffu, e, 8);
    e += __shfl_xor_sync(0xffffffffu, e, 16);

    __shared__ float sm[8], se[8], su[8];
    if (lane == 0) { sm[warp] = mse_acc; se[warp] = e; su[warp] = ue_n; }
    __syncthreads();

    if (tid == 0) {
        float tm = 0.f, te = 0.f, tu = 0.f;
        #pragma unroll
        for (int i = 0; i < 8; i++) { tm += sm[i]; te += se[i]; tu += su[i]; }
        atomicAdd(&g_mse, (double)tm);
        atomicAdd(&g_ie,  (double)te);
        atomicAdd(&g_ue,  (double)tu);
        __threadfence();
        const unsigned old = atomicAdd(&g_count, 1u);
        if (old == gridDim.x - 1) {
            u64 mb  = atomicExch((u64*)&g_mse, 0ull);
            u64 eb  = atomicExch((u64*)&g_ie,  0ull);
            u64 ub2 = atomicExch((u64*)&g_ue,  0ull);
            const double mse = __longlong_as_double((long long)mb);
            const double ie  = __longlong_as_double((long long)eb);
            const double ue  = __longlong_as_double((long long)ub2);
            const double n_bk = (double)NB * (double)NK;
            out[NB * NK] = (float)(mse / n_bk + REG * (ue / (double)NB)
                                              + REG * (ie / n_bk));
            atomicExch(&g_count, 0u);
        }
    }
}

extern "C" void kernel_launch(void* const* d_in, const int* in_sizes, int n_in,
                              void* d_out, int out_size) {
    const float* user_weight = (const float*)d_in[0];
    const float* item_weight = (const float*)d_in[1];
    const float* user_bias   = (const float*)d_in[2];
    const float* item_bias   = (const float*)d_in[3];
    const float* bias        = (const float*)d_in[4];
    const float* target      = (const float*)d_in[5];
    const int*   user        = (const int*)d_in[6];
    const int*   item        = (const int*)d_in[7];

    mf_main<<<NB / 8, 256>>>(user_weight, item_weight, user_bias, item_bias,
                             bias, target, user, item, (float*)d_out);
}

// round 8
// speedup vs baseline: 2.7310x; 1.0307x over previous
#include <cuda_runtime.h>
#include <cstdint>

#define NB 16384      // B
#define NK 50         // K
#define NH 64         // H
#define REG 0.01
#define DEPTH 3       // cp.async ring depth (stages)
#define NSTAGE 13     // 12 full stages of 4 items + 1 tail stage of 2

typedef unsigned long long u64;

static __device__ __forceinline__ u64 pack2(float lo, float hi) {
    u64 r; asm("mov.b64 %0, {%1,%2};" : "=l"(r) : "f"(lo), "f"(hi)); return r;
}
static __device__ __forceinline__ void unpack2(u64 v, float& lo, float& hi) {
    asm("mov.b64 {%0,%1}, %2;" : "=f"(lo), "=f"(hi) : "l"(v));
}
static __device__ __forceinline__ u64 add2(u64 a, u64 b) {
    u64 r; asm("add.rn.f32x2 %0, %1, %2;" : "=l"(r) : "l"(a), "l"(b)); return r;
}
static __device__ __forceinline__ u64 mul2(u64 a, u64 b) {
    u64 r; asm("mul.rn.f32x2 %0, %1, %2;" : "=l"(r) : "l"(a), "l"(b)); return r;
}
static __device__ __forceinline__ u64 fma2(u64 a, u64 b, u64 c) {
    u64 r; asm("fma.rn.f32x2 %0, %1, %2, %3;" : "=l"(r) : "l"(a), "l"(b), "l"(c)); return r;
}
static __device__ __forceinline__ void cpa16(uint32_t dst, const void* src) {
    asm volatile("cp.async.cg.shared.global [%0], [%1], 16;\n" :: "r"(dst), "l"(src));
}

__device__ double g_mse, g_ue, g_ie;        // zero-init; self-reset each run
__device__ unsigned int g_count;

__global__ __launch_bounds__(256, 6) void mf_main(
    const float* __restrict__ user_weight,   // [100000, 64]
    const float* __restrict__ item_weight,   // [1000000, 64]
    const float* __restrict__ user_bias,     // [100000, 1]
    const float* __restrict__ item_bias,     // [1000000, 1]
    const float* __restrict__ bias,          // [1]
    const float* __restrict__ target,        // [B, K]
    const int*   __restrict__ user,          // [B]
    const int*   __restrict__ item,          // [B, K]
    float* __restrict__ out)                 // [B*K + 1]
{
    const int tid  = threadIdx.x;
    const int warp = tid >> 5;               // 8 warps, one user each
    const int lane = tid & 31;
    const int g    = lane >> 3;              // group 0..3 within warp
    const int s    = lane & 7;               // H-slice owner (32B each)
    const int b    = blockIdx.x * 8 + warp;

    __shared__ int   s_items[8 * NK];
    __shared__ float s_pred[8 * NK];
    __shared__ __align__(16) char s_ring[8 * DEPTH * 4 * 256];  // 24 KB

    const int base = blockIdx.x * 8 * NK;
    for (int i = tid; i < 8 * NK; i += 256) s_items[i] = item[base + i];

    // --- user embedding slice: contiguous floats [8s .. 8s+7] ---
    const int u = user[b];
    const float ubv = __ldg(user_bias + u);
    const u64 ubp = pack2(ubv, ubv);
    const float* uwr = user_weight + (size_t)u * NH + s * 8;
    ulonglong2 ur0 = __ldg((const ulonglong2*)uwr);
    ulonglong2 ur1 = __ldg((const ulonglong2*)(uwr + 4));
    const u64 u0 = add2(ur0.x, ubp);
    const u64 u1 = add2(ur0.y, ubp);
    const u64 u2 = add2(ur1.x, ubp);
    const u64 u3 = add2(ur1.y, ubp);
    const float bias0 = __ldg(bias);

    __syncthreads();
    const int* myitems = s_items + warp * NK;
    const uint32_t my_ring =
        (uint32_t)__cvta_generic_to_shared(s_ring) + warp * (DEPTH * 1024)
        + g * 256 + s * 32;

    // stage t item index for this group (tail stage: groups >=2 fetch a dummy
    // valid row, never consumed)
    #define STAGE_K(t) (((t) < 12) ? (4 * (t) + g) : ((g < 2) ? (48 + g) : g))
    #define SLOT(t) (((t) % DEPTH) * 1024)

    // --- prologue: fill stages 0..DEPTH-2 ---
    #pragma unroll
    for (int t = 0; t < DEPTH - 1; t++) {
        const int idx = myitems[STAGE_K(t)];
        const float* row = item_weight + (size_t)idx * NH + s * 8;
        const uint32_t dst = my_ring + SLOT(t);
        cpa16(dst, row);
        cpa16(dst + 16, row + 4);
        asm volatile("cp.async.commit_group;\n");
    }
    // bias register pipeline (depth 2)
    float fb[2];
    fb[0] = __ldg(item_bias + myitems[STAGE_K(0)]);
    fb[1] = __ldg(item_bias + myitems[STAGE_K(1)]);

    float ie_acc = 0.0f;                     // valid on s==0 lanes

    #pragma unroll
    for (int t = 0; t < NSTAGE; t++) {
        // issue stage t+DEPTH-1 (commit empty groups near the end to keep
        // wait_group counting uniform)
        if (t + DEPTH - 1 < NSTAGE) {
            const int tt = t + DEPTH - 1;
            const int idx = myitems[STAGE_K(tt)];
            const float* row = item_weight + (size_t)idx * NH + s * 8;
            const uint32_t dst = my_ring + SLOT(tt);
            cpa16(dst, row);
            cpa16(dst + 16, row + 4);
        }
        asm volatile("cp.async.commit_group;\n");

        const float ib = fb[t & 1];
        if (t + 2 < NSTAGE)
            fb[t & 1] = __ldg(item_bias + myitems[STAGE_K(t + 2)]);

        // stage t guaranteed complete when <= DEPTH-1 newer groups pending
        asm volatile("cp.async.wait_group %0;\n" :: "n"(DEPTH - 1));

        // consume own 32B slice (written by this lane -> no sync needed)
        const uint32_t srcp = my_ring + SLOT(t);
        u64 x0, x1, x2, x3;
        asm volatile("ld.shared.v2.u64 {%0,%1}, [%2];"
                     : "=l"(x0), "=l"(x1) : "r"(srcp));
        asm volatile("ld.shared.v2.u64 {%0,%1}, [%2];"
                     : "=l"(x2), "=l"(x3) : "r"(srcp + 16));

        const u64 ibp = pack2(ib, ib);
        x0 = add2(x0, ibp); x1 = add2(x1, ibp);
        x2 = add2(x2, ibp); x3 = add2(x3, ibp);
        u64 d2 = mul2(u0, x0); d2 = fma2(u1, x1, d2);
        d2 = fma2(u2, x2, d2); d2 = fma2(u3, x3, d2);
        u64 q2 = mul2(x0, x0); q2 = fma2(x1, x1, q2);
        q2 = fma2(x2, x2, q2); q2 = fma2(x3, x3, q2);
        float dl, dh, ql, qh;
        unpack2(d2, dl, dh); unpack2(q2, ql, qh);
        float d = dl + dh, q = ql + qh;
        #pragma unroll
        for (int o = 1; o < 8; o <<= 1) {
            d += __shfl_xor_sync(0xffffffffu, d, o);
            q += __shfl_xor_sync(0xffffffffu, q, o);
        }
        const bool active = (t < 12) || (g < 2);
        if (s == 0 && active) {
            s_pred[warp * NK + STAGE_K(t)] = d + bias0;
            ie_acc += sqrtf(q);
        }
    }
    #undef STAGE_K
    #undef SLOT

    __syncwarp();

    // --- coalesced epilogue: preds out, targets in, mse per lane ---
    float mse_acc = 0.0f;
    #pragma unroll
    for (int i = lane; i < NK; i += 32) {
        const float pred = s_pred[warp * NK + i];
        const float diff = pred - __ldcs(target + b * NK + i);
        mse_acc = fmaf(diff, diff, mse_acc);
        __stcs(out + b * NK + i, pred);
    }
    #pragma unroll
    for (int o = 1; o < 32; o <<= 1)
        mse_acc += __shfl_xor_sync(0xffffffffu, mse_acc, o);

    // --- ||ue|| ---
    u64 uq2 = mul2(u0, u0); uq2 = fma2(u1, u1, uq2);
    uq2 = fma2(u2, u2, uq2); uq2 = fma2(u3, u3, uq2);
    float ul, uh; unpack2(uq2, ul, uh);
    float uq = ul + uh;
    #pragma unroll
    for (int o = 1; o < 8; o <<= 1)
        uq += __shfl_xor_sync(0xffffffffu, uq, o);
    const float ue_n = sqrtf(uq);             // valid on every s==0 lane

    // reduce ie across the four s==0 lanes (0,8,16,24)
    float e = (s == 0) ? ie_acc : 0.0f;
    e += __shfl_xor_sync(0xffffffffu, e, 8);
    e += __shfl_xor_sync(0xffffffffu, e, 16);

    __shared__ float sm[8], se[8], su[8];
    if (lane == 0) { sm[warp] = mse_acc; se[warp] = e; su[warp] = ue_n; }
    __syncthreads();

    if (tid == 0) {
        float tm = 0.f, te = 0.f, tu = 0.f;
        #pragma unroll
        for (int i = 0; i < 8; i++) { tm += sm[i]; te += se[i]; tu += su[i]; }
        atomicAdd(&g_mse, (double)tm);
        atomicAdd(&g_ie,  (double)te);
        atomicAdd(&g_ue,  (double)tu);
        __threadfence();
        const unsigned old = atomicAdd(&g_count, 1u);
        if (old == gridDim.x - 1) {
            u64 mb  = atomicExch((u64*)&g_mse, 0ull);
            u64 eb  = atomicExch((u64*)&g_ie,  0ull);
            u64 ub2 = atomicExch((u64*)&g_ue,  0ull);
            const double mse = __longlong_as_double((long long)mb);
            const double ie  = __longlong_as_double((long long)eb);
            const double ue  = __longlong_as_double((long long)ub2);
            const double n_bk = (double)NB * (double)NK;
            out[NB * NK] = (float)(mse / n_bk + REG * (ue / (double)NB)
                                              + REG * (ie / n_bk));
            atomicExch(&g_count, 0u);
        }
    }
}

extern "C" void kernel_launch(void* const* d_in, const int* in_sizes, int n_in,
                              void* d_out, int out_size) {
    const float* user_weight = (const float*)d_in[0];
    const float* item_weight = (const float*)d_in[1];
    const float* user_bias   = (const float*)d_in[2];
    const float* item_bias   = (const float*)d_in[3];
    const float* bias        = (const float*)d_in[4];
    const float* target      = (const float*)d_in[5];
    const int*   user        = (const int*)d_in[6];
    const int*   item        = (const int*)d_in[7];

    mf_main<<<NB / 8, 256>>>(user_weight, item_weight, user_bias, item_bias,
                             bias, target, user, item, (float*)d_out);
}